// round 1
// baseline (speedup 1.0000x reference)
#include <cuda_runtime.h>
#include <cuda_bf16.h>
#include <cstdint>

// Problem constants (from reference_code)
#define N_NODES 50000
#define N_EDGES 800000
#define F 128            // IN_F == OUT_F == 128

// ---------------------------------------------------------------------------
// Device-global scratch (allocation-free rule: __device__ arrays only)
// ---------------------------------------------------------------------------
__device__ float g_support[(size_t)N_NODES * F];   // X @ W  (25.6 MB, fits L2)
__device__ int   g_deg[N_NODES];                   // per-destination-row degree
__device__ int   g_rowstart[N_NODES];              // exclusive scan of g_deg
__device__ int   g_cursor[N_NODES];                // scatter cursors
__device__ int   g_csr_col[N_EDGES];               // source node per slot
__device__ float g_csr_val[N_EDGES];               // edge value per slot
__device__ int   g_bsum[64];                       // scan block sums

#define SCAN_CHUNK 1024
#define SCAN_NBLK  ((N_NODES + SCAN_CHUNK - 1) / SCAN_CHUNK)   // 49

// ---------------------------------------------------------------------------
// 0) zero counters
// ---------------------------------------------------------------------------
__global__ void k_zero() {
    int i = blockIdx.x * blockDim.x + threadIdx.x;
    if (i < N_NODES) { g_deg[i] = 0; g_cursor[i] = 0; }
}

// ---------------------------------------------------------------------------
// 1) count edges per destination row
// ---------------------------------------------------------------------------
__global__ void k_count(const int* __restrict__ edge_row) {
    int e = blockIdx.x * blockDim.x + threadIdx.x;
    if (e < N_EDGES) atomicAdd(&g_deg[edge_row[e]], 1);
}

// ---------------------------------------------------------------------------
// 2) exclusive scan of g_deg -> g_rowstart  (3 tiny kernels)
// ---------------------------------------------------------------------------
__global__ void k_scan1() {
    __shared__ int s[SCAN_CHUNK];
    int tid = threadIdx.x;
    int i = blockIdx.x * SCAN_CHUNK + tid;
    int v = (i < N_NODES) ? g_deg[i] : 0;
    s[tid] = v;
    __syncthreads();
#pragma unroll
    for (int off = 1; off < SCAN_CHUNK; off <<= 1) {
        int t = (tid >= off) ? s[tid - off] : 0;
        __syncthreads();
        s[tid] += t;
        __syncthreads();
    }
    if (i < N_NODES) g_rowstart[i] = s[tid] - v;   // exclusive within block
    if (tid == SCAN_CHUNK - 1) g_bsum[blockIdx.x] = s[tid];
}

__global__ void k_scan2() {
    if (threadIdx.x == 0 && blockIdx.x == 0) {
        int run = 0;
        for (int b = 0; b < SCAN_NBLK; b++) {
            int t = g_bsum[b];
            g_bsum[b] = run;
            run += t;
        }
    }
}

__global__ void k_scan3() {
    int i = blockIdx.x * SCAN_CHUNK + threadIdx.x;
    if (i < N_NODES) g_rowstart[i] += g_bsum[blockIdx.x];
}

// ---------------------------------------------------------------------------
// 3) scatter edges into destination-CSR slots
// ---------------------------------------------------------------------------
__global__ void k_scatter(const int* __restrict__ edge_row,
                          const int* __restrict__ edge_col,
                          const float* __restrict__ edge_val) {
    int e = blockIdx.x * blockDim.x + threadIdx.x;
    if (e >= N_EDGES) return;
    int r = edge_row[e];
    int pos = g_rowstart[r] + atomicAdd(&g_cursor[r], 1);
    g_csr_col[pos] = edge_col[e];
    g_csr_val[pos] = edge_val[e];
}

// ---------------------------------------------------------------------------
// 4) GEMM: g_support = X @ W   (fp32 SIMT, W staged once in smem)
//    Block: 256 threads, computes 64 rows x 128 cols.
//    warp w -> rows [w*8, w*8+8), lane l -> cols [4l, 4l+4)
// ---------------------------------------------------------------------------
#define GEMM_ROWS 64
#define GEMM_THREADS 256

__global__ void __launch_bounds__(GEMM_THREADS, 2)
k_gemm(const float* __restrict__ x, const float* __restrict__ w) {
    extern __shared__ float sm[];
    float* sW = sm;               // 128*128 = 16384 floats (64 KB)
    float* sX = sm + 128 * 128;   // 64*128  =  8192 floats (32 KB)

    int tid = threadIdx.x;
    int row0 = blockIdx.x * GEMM_ROWS;

    // stage W (row-major [k][n]) as float4
    const float4* w4 = (const float4*)w;
    float4* sW4 = (float4*)sW;
    for (int i = tid; i < 128 * 128 / 4; i += GEMM_THREADS) sW4[i] = w4[i];

    // stage X tile
    float4* sX4 = (float4*)sX;
    for (int i = tid; i < GEMM_ROWS * 128 / 4; i += GEMM_THREADS) {
        int r = i >> 5;          // 32 float4 per row
        int c4 = i & 31;
        int gr = row0 + r;
        float4 v = make_float4(0.f, 0.f, 0.f, 0.f);
        if (gr < N_NODES) v = ((const float4*)(x + (size_t)gr * F))[c4];
        sX4[i] = v;
    }
    __syncthreads();

    int warp = tid >> 5;
    int lane = tid & 31;
    int r0 = warp * 8;

    float4 acc[8];
#pragma unroll
    for (int r = 0; r < 8; r++) acc[r] = make_float4(0.f, 0.f, 0.f, 0.f);

#pragma unroll 8
    for (int kk = 0; kk < 128; kk++) {
        float4 wv = sW4[kk * 32 + lane];
#pragma unroll
        for (int r = 0; r < 8; r++) {
            float xv = sX[(r0 + r) * 128 + kk];   // warp-broadcast
            acc[r].x = fmaf(xv, wv.x, acc[r].x);
            acc[r].y = fmaf(xv, wv.y, acc[r].y);
            acc[r].z = fmaf(xv, wv.z, acc[r].z);
            acc[r].w = fmaf(xv, wv.w, acc[r].w);
        }
    }

#pragma unroll
    for (int r = 0; r < 8; r++) {
        int gr = row0 + r0 + r;
        if (gr < N_NODES)
            ((float4*)(g_support + (size_t)gr * F))[lane] = acc[r];
    }
}

// ---------------------------------------------------------------------------
// 5) SpMM: one warp per destination row, atomic-free accumulation.
//    lane l accumulates cols [4l, 4l+4); bias folded into init.
// ---------------------------------------------------------------------------
__global__ void k_spmm(const float* __restrict__ bias,
                       float* __restrict__ out) {
    int gtid = blockIdx.x * blockDim.x + threadIdx.x;
    int row = gtid >> 5;
    int lane = gtid & 31;
    if (row >= N_NODES) return;

    int start = g_rowstart[row];
    int deg = g_deg[row];

    float4 acc = ((const float4*)bias)[lane];

    for (int j = 0; j < deg; j++) {
        int c = g_csr_col[start + j];      // warp-uniform broadcast
        float v = g_csr_val[start + j];
        float4 s = ((const float4*)(g_support + (size_t)c * F))[lane];
        acc.x = fmaf(v, s.x, acc.x);
        acc.y = fmaf(v, s.y, acc.y);
        acc.z = fmaf(v, s.z, acc.z);
        acc.w = fmaf(v, s.w, acc.w);
    }

    ((float4*)(out + (size_t)row * F))[lane] = acc;
}

// ---------------------------------------------------------------------------
// launcher
// ---------------------------------------------------------------------------
extern "C" void kernel_launch(void* const* d_in, const int* in_sizes, int n_in,
                              void* d_out, int out_size) {
    const float* x        = (const float*)d_in[0];
    const int*   edge_row = (const int*)d_in[1];
    const int*   edge_col = (const int*)d_in[2];
    const float* edge_val = (const float*)d_in[3];
    const float* weight   = (const float*)d_in[4];
    const float* bias     = (const float*)d_in[5];
    float* out = (float*)d_out;

    (void)in_sizes; (void)n_in; (void)out_size;

    // CSR build
    {
        int blk = 256;
        k_zero<<<(N_NODES + blk - 1) / blk, blk>>>();
        k_count<<<(N_EDGES + blk - 1) / blk, blk>>>(edge_row);
        k_scan1<<<SCAN_NBLK, SCAN_CHUNK>>>();
        k_scan2<<<1, 32>>>();
        k_scan3<<<SCAN_NBLK, SCAN_CHUNK>>>();
        k_scatter<<<(N_EDGES + blk - 1) / blk, blk>>>(edge_row, edge_col, edge_val);
    }

    // GEMM (96 KB dynamic smem)
    {
        static bool attr_set = false;
        if (!attr_set) {
            cudaFuncSetAttribute(k_gemm, cudaFuncAttributeMaxDynamicSharedMemorySize,
                                 96 * 1024);
            attr_set = true;
        }
        int grid = (N_NODES + GEMM_ROWS - 1) / GEMM_ROWS;   // 782
        k_gemm<<<grid, GEMM_THREADS, 96 * 1024>>>(x, weight);
    }

    // SpMM + bias
    {
        int threads = 256;
        long total = (long)N_NODES * 32;
        int grid = (int)((total + threads - 1) / threads);  // 6250
        k_spmm<<<grid, threads>>>(bias, out);
    }
}